// round 3
// baseline (speedup 1.0000x reference)
#include <cuda_runtime.h>
#include <cuda_bf16.h>
#include <cstdint>

typedef unsigned long long u64;

#define NP 16384
#define NG 16384
#define NY 8              // gt segments (grid.y)
#define SEG (NG / NY)     // 2048 gt per block
#define TILE 128
#define NT (SEG / TILE)   // 16 gt tiles per block

#define INF_BITS 0x7f800000u
#define FLT_BIG 3.402823466e38f

// Scratch (device globals). Encoded as key = INF_BITS - float_bits(min), so
// zero (static init / post-run reset) decodes to +inf and atomicMax == float-min.
__device__ unsigned int g_key_pred[NP];   // zero-initialized at module load
__device__ unsigned int g_key_gt[NG];

// ---------------------------------------------------------------------------
// packed f32x2 helpers
// ---------------------------------------------------------------------------
__device__ __forceinline__ u64 fma2(u64 a, u64 b, u64 c) {
    u64 d; asm("fma.rn.f32x2 %0, %1, %2, %3;" : "=l"(d) : "l"(a), "l"(b), "l"(c)); return d;
}
__device__ __forceinline__ u64 add2(u64 a, u64 b) {
    u64 d; asm("add.rn.f32x2 %0, %1, %2;" : "=l"(d) : "l"(a), "l"(b)); return d;
}
__device__ __forceinline__ u64 pack2(float lo, float hi) {
    u64 d; asm("mov.b64 %0, {%1, %2};" : "=l"(d) : "f"(lo), "f"(hi)); return d;
}
__device__ __forceinline__ float lo32(u64 v) { return __uint_as_float((unsigned)v); }
__device__ __forceinline__ float hi32(u64 v) { return __uint_as_float((unsigned)(v >> 32)); }

// ---------------------------------------------------------------------------
// Kernel 1: fused tiled pairwise-min, packed fp32x2 inner loop.
// Block 256 threads: tx = tid&15 (gt cols), ty = tid>>4 (pred rows).
// Thread tile: 8 pred rows (ty + 16*ii) x 8 gt cols ({2tx, 2tx+1} + 32*jj).
// t = dot(-2p, g) + |g|^2  (row min in t-space, +|p|^2 folded at the end).
// v = t + |p|^2            (col min).  Clamp applied after the mins.
// ---------------------------------------------------------------------------
__global__ __launch_bounds__(256, 2)
void k_pairs(const float* __restrict__ pp, const float* __restrict__ gp) {
    __shared__ __align__(16) float sgx[2][TILE], sgy[2][TILE], sgz[2][TILE], sgq[2][TILE];
    __shared__ __align__(16) u64 sax[TILE], say[TILE], saz[TILE], spq[TILE];  // dup'd pred
    __shared__ float sred[TILE * 17];

    const int tid = threadIdx.x;
    const int tx = tid & 15;
    const int ty = tid >> 4;
    const int bx = blockIdx.x;   // pred tile (0..127)
    const int by = blockIdx.y;   // gt segment (0..NY-1)
    const bool stager = (tid < TILE);

    // Stage pred tile: a = -2p (duplicated pairs) and |p|^2
    if (stager) {
        int idx = bx * TILE + tid;
        float x = pp[3 * idx + 0];
        float y = pp[3 * idx + 1];
        float z = pp[3 * idx + 2];
        float q = x * x + y * y + z * z;
        sax[tid] = pack2(-2.0f * x, -2.0f * x);
        say[tid] = pack2(-2.0f * y, -2.0f * y);
        saz[tid] = pack2(-2.0f * z, -2.0f * z);
        spq[tid] = pack2(q, q);
        // stage gt tile 0
        int g0 = by * SEG + tid;
        float gx = gp[3 * g0 + 0];
        float gy = gp[3 * g0 + 1];
        float gz = gp[3 * g0 + 2];
        sgx[0][tid] = gx; sgy[0][tid] = gy; sgz[0][tid] = gz;
        sgq[0][tid] = gx * gx + gy * gy + gz * gz;
    }
    __syncthreads();

    float rmin[8];
#pragma unroll
    for (int i = 0; i < 8; i++) rmin[i] = FLT_BIG;

    for (int t = 0; t < NT; t++) {
        const int cur = t & 1;
        // prefetch next gt tile into registers (hidden behind compute)
        float nx = 0.f, ny = 0.f, nz = 0.f;
        if (stager && t + 1 < NT) {
            int gi = by * SEG + (t + 1) * TILE + tid;
            nx = gp[3 * gi + 0]; ny = gp[3 * gi + 1]; nz = gp[3 * gi + 2];
        }

        // load 8 gt columns as 4 packed pairs
        u64 gx2[4], gy2[4], gz2[4], gq2[4];
#pragma unroll
        for (int jj = 0; jj < 4; jj++) {
            int c = 2 * tx + 32 * jj;
            gx2[jj] = *(const u64*)&sgx[cur][c];
            gy2[jj] = *(const u64*)&sgy[cur][c];
            gz2[jj] = *(const u64*)&sgz[cur][c];
            gq2[jj] = *(const u64*)&sgq[cur][c];
        }

        float cminA[4], cminB[4];
#pragma unroll
        for (int jj = 0; jj < 4; jj++) { cminA[jj] = FLT_BIG; cminB[jj] = FLT_BIG; }

#pragma unroll
        for (int ii = 0; ii < 8; ii++) {
            const int i = ty + 16 * ii;
            const u64 ax2 = sax[i], ay2 = say[i], az2 = saz[i], pq2 = spq[i];
#pragma unroll
            for (int jj = 0; jj < 4; jj++) {
                u64 t2 = fma2(az2, gz2[jj], gq2[jj]);
                t2 = fma2(ay2, gy2[jj], t2);
                t2 = fma2(ax2, gx2[jj], t2);
                // row min (t-space)
                rmin[ii] = fminf(rmin[ii], fminf(lo32(t2), hi32(t2)));
                // col min (needs +|p|^2)
                u64 v2 = add2(pq2, t2);
                cminA[jj] = fminf(cminA[jj], lo32(v2));
                cminB[jj] = fminf(cminB[jj], hi32(v2));
            }
        }

        __syncthreads();   // prior col reduction done -> sred free
#pragma unroll
        for (int jj = 0; jj < 4; jj++) {
            int c = 2 * tx + 32 * jj;
            sred[c * 17 + ty] = cminA[jj];
            sred[(c + 1) * 17 + ty] = cminB[jj];
        }
        // commit prefetched tile
        if (stager && t + 1 < NT) {
            const int nb = cur ^ 1;
            sgx[nb][tid] = nx; sgy[nb][tid] = ny; sgz[nb][tid] = nz;
            sgq[nb][tid] = nx * nx + ny * ny + nz * nz;
        }
        __syncthreads();   // sred + next tile ready

        if (stager) {
            float m = sred[tid * 17];
#pragma unroll
            for (int k = 1; k < 16; k++) m = fminf(m, sred[tid * 17 + k]);
            m = fmaxf(m, 0.0f);
            atomicMax(&g_key_gt[by * SEG + t * TILE + tid], INF_BITS - __float_as_uint(m));
        }
    }

    // row (pred) reduction across tx
    __syncthreads();
#pragma unroll
    for (int ii = 0; ii < 8; ii++)
        sred[(ty + 16 * ii) * 17 + tx] = rmin[ii];
    __syncthreads();
    if (stager) {
        float m = sred[tid * 17];
#pragma unroll
        for (int k = 1; k < 16; k++) m = fminf(m, sred[tid * 17 + k]);
        m = fmaxf(lo32(spq[tid]) + m, 0.0f);   // back to d2-space, clamp
        atomicMax(&g_key_pred[bx * TILE + tid], INF_BITS - __float_as_uint(m));
    }
}

// ---------------------------------------------------------------------------
// Kernel 2: weighted sums + final combine + scratch reset (single block).
// Deterministic: fixed per-thread slices, fixed reduction tree.
// ---------------------------------------------------------------------------
__global__ __launch_bounds__(512, 1)
void k_combine(const float* __restrict__ wp, const float* __restrict__ wg,
               float* __restrict__ out) {
    __shared__ float sh[4][16];
    const int tid = threadIdx.x;
    const int lane = tid & 31;
    const int wid = tid >> 5;

    float a0 = 0.f, a1 = 0.f, a2 = 0.f, a3 = 0.f;
#pragma unroll 4
    for (int k = 0; k < NP / 512; k++) {
        int i = k * 512 + tid;
        unsigned kp = g_key_pred[i];
        unsigned kg = g_key_gt[i];
        g_key_pred[i] = 0u;   // reset for next replay
        g_key_gt[i] = 0u;
        float mp = __uint_as_float(INF_BITS - kp);
        float mg = __uint_as_float(INF_BITS - kg);
        float w = wp[i];
        float w2 = wg[i];
        a0 += w * mp;  a1 += w;
        a2 += w2 * mg; a3 += w2;
    }
#pragma unroll
    for (int o = 16; o > 0; o >>= 1) {
        a0 += __shfl_down_sync(0xffffffffu, a0, o);
        a1 += __shfl_down_sync(0xffffffffu, a1, o);
        a2 += __shfl_down_sync(0xffffffffu, a2, o);
        a3 += __shfl_down_sync(0xffffffffu, a3, o);
    }
    if (lane == 0) { sh[0][wid] = a0; sh[1][wid] = a1; sh[2][wid] = a2; sh[3][wid] = a3; }
    __syncthreads();
    if (tid == 0) {
        float s0 = 0.f, s1 = 0.f, s2 = 0.f, s3 = 0.f;
#pragma unroll
        for (int w = 0; w < 16; w++) {
            s0 += sh[0][w]; s1 += sh[1][w]; s2 += sh[2][w]; s3 += sh[3][w];
        }
        out[0] = s0 / fmaxf(s1, 1e-9f) + s2 / fmaxf(s3, 1e-9f);
    }
}

// ---------------------------------------------------------------------------
extern "C" void kernel_launch(void* const* d_in, const int* in_sizes, int n_in,
                              void* d_out, int out_size) {
    const float* pred = (const float*)d_in[0];   // (P,3)
    const float* gt   = (const float*)d_in[1];   // (G,3)
    const float* wp   = (const float*)d_in[2];   // (P,)
    const float* wg   = (const float*)d_in[3];   // (G,)
    float* out = (float*)d_out;

    dim3 grid(NP / TILE, NY);
    k_pairs<<<grid, 256>>>(pred, gt);
    k_combine<<<1, 512>>>(wp, wg, out);
}

// round 4
// speedup vs baseline: 1.8047x; 1.8047x over previous
#include <cuda_runtime.h>
#include <cuda_bf16.h>
#include <cstdint>

#define NP 16384
#define NG 16384
#define NY 8              // gt segments (grid.y)
#define SEG (NG / NY)     // 2048 gt per block
#define TILE 128
#define NT (SEG / TILE)   // 16 gt tiles per block

#define INF_BITS 0x7f800000u
#define FLT_BIG 3.402823466e38f

// Scratch (device globals, zero-initialized at module load).
// key = INF_BITS - float_bits(min): zero decodes to +inf, atomicMax == float-min.
// Combine kernel resets keys + counter to zero for the next graph replay.
__device__ unsigned int g_key_pred[NP];
__device__ unsigned int g_key_gt[NG];
__device__ float        g_part[32][4];
__device__ unsigned int g_ctr;

// ---------------------------------------------------------------------------
// Kernel 1: fused tiled pairwise-min (scalar fp32, 6 ops/pair, 4 on fma pipe).
// Block 256 threads: tx = tid&15 (gt cols), ty = tid>>4 (pred rows).
// Thread tile: 8 pred rows (ty+16*i) x 8 gt cols (tx+16*j).
//   a = -2p (staged),  t = ax*gx + ay*gy + az*gz + |g|^2
//   row min over t (add |p|^2 once at end);  col min over v = t + |p|^2.
// Clamp max(.,0) applied after the mins (monotone-commutes with min).
// One __syncthreads per tile: double-buffered gt tile AND reduction scratch.
// ---------------------------------------------------------------------------
__global__ __launch_bounds__(256, 2)
void k_pairs(const float* __restrict__ pp, const float* __restrict__ gp) {
    __shared__ __align__(16) float4 sp[TILE];          // (-2x,-2y,-2z,|p|^2)
    __shared__ __align__(16) float4 sg[2][TILE];       // (x,y,z,|g|^2)
    __shared__ float sred[2][TILE * 17];

    const int tid = threadIdx.x;
    const int tx = tid & 15;
    const int ty = tid >> 4;
    const int bx = blockIdx.x;           // pred tile (0..127)
    const int by = blockIdx.y;           // gt segment (0..NY-1)
    const bool stager = (tid < TILE);

    if (stager) {
        int pi = bx * TILE + tid;
        float x = pp[3 * pi + 0];
        float y = pp[3 * pi + 1];
        float z = pp[3 * pi + 2];
        sp[tid] = make_float4(-2.0f * x, -2.0f * y, -2.0f * z, x * x + y * y + z * z);
        int gi = by * SEG + tid;
        float gx = gp[3 * gi + 0];
        float gy = gp[3 * gi + 1];
        float gz = gp[3 * gi + 2];
        sg[0][tid] = make_float4(gx, gy, gz, gx * gx + gy * gy + gz * gz);
    }
    __syncthreads();

    // pred tile -> registers, once per block
    float ax[8], ay[8], az[8], pq[8], rmin[8];
#pragma unroll
    for (int i = 0; i < 8; i++) {
        float4 v = sp[ty + 16 * i];
        ax[i] = v.x; ay[i] = v.y; az[i] = v.z; pq[i] = v.w;
        rmin[i] = FLT_BIG;
    }

    for (int t = 0; t < NT; t++) {
        const int cur = t & 1;

        // issue next-tile prefetch early (latency hidden behind compute)
        float nx = 0.f, ny = 0.f, nz = 0.f;
        if (stager && t + 1 < NT) {
            int gi = by * SEG + (t + 1) * TILE + tid;
            nx = gp[3 * gi + 0]; ny = gp[3 * gi + 1]; nz = gp[3 * gi + 2];
        }

        float gx[8], gy[8], gz[8], gq[8], cmin[8];
#pragma unroll
        for (int j = 0; j < 8; j++) {
            float4 v = sg[cur][tx + 16 * j];
            gx[j] = v.x; gy[j] = v.y; gz[j] = v.z; gq[j] = v.w;
            cmin[j] = FLT_BIG;
        }

#pragma unroll
        for (int i = 0; i < 8; i++) {
#pragma unroll
            for (int j = 0; j < 8; j++) {
                float d = fmaf(az[i], gz[j], gq[j]);
                d = fmaf(ay[i], gy[j], d);
                d = fmaf(ax[i], gx[j], d);             // 3 FFMA
                rmin[i] = fminf(rmin[i], d);           // FMNMX (t-space)
                cmin[j] = fminf(cmin[j], d + pq[i]);   // FADD + FMNMX
            }
        }

        // stash column mins for this tile (buffer 'cur')
#pragma unroll
        for (int j = 0; j < 8; j++)
            sred[cur][(tx + 16 * j) * 17 + ty] = cmin[j];

        // commit prefetched gt tile into the other buffer
        if (stager && t + 1 < NT)
            sg[cur ^ 1][tid] = make_float4(nx, ny, nz, nx * nx + ny * ny + nz * nz);

        __syncthreads();   // single barrier per tile

        // epilogue for tile t: column reduction + global min
        if (stager) {
            float m = sred[cur][tid * 17];
#pragma unroll
            for (int k = 1; k < 16; k++) m = fminf(m, sred[cur][tid * 17 + k]);
            m = fmaxf(m, 0.0f);
            atomicMax(&g_key_gt[by * SEG + t * TILE + tid], INF_BITS - __float_as_uint(m));
        }
    }

    // row reduction: last tile used sred[(NT-1)&1]=sred[1]; rows use sred[0]
#pragma unroll
    for (int i = 0; i < 8; i++)
        sred[0][(ty + 16 * i) * 17 + tx] = rmin[i];
    __syncthreads();
    if (stager) {
        float m = sred[0][tid * 17];
#pragma unroll
        for (int k = 1; k < 16; k++) m = fminf(m, sred[0][tid * 17 + k]);
        m = fmaxf(sp[tid].w + m, 0.0f);   // back to d2-space, clamp
        atomicMax(&g_key_pred[bx * TILE + tid], INF_BITS - __float_as_uint(m));
    }
}

// ---------------------------------------------------------------------------
// Kernel 2: weighted partial sums (32 blocks) + last-block final combine.
// Deterministic: fixed slices, fixed reduction order; result independent of
// which block finishes last. Resets scratch (keys + counter) for next replay.
// ---------------------------------------------------------------------------
__global__ __launch_bounds__(256, 1)
void k_combine(const float* __restrict__ wp, const float* __restrict__ wg,
               float* __restrict__ out) {
    __shared__ float sh[4][8];
    __shared__ unsigned int s_ticket;
    const int b = blockIdx.x;
    const int tid = threadIdx.x;
    const int lane = tid & 31;
    const int wid = tid >> 5;

    float a0 = 0.f, a1 = 0.f, a2 = 0.f, a3 = 0.f;
#pragma unroll
    for (int k = 0; k < 2; k++) {
        int i = b * 512 + k * 256 + tid;
        unsigned kp = g_key_pred[i];
        unsigned kg = g_key_gt[i];
        g_key_pred[i] = 0u;   // reset for next replay
        g_key_gt[i]   = 0u;
        float mp = __uint_as_float(INF_BITS - kp);
        float mg = __uint_as_float(INF_BITS - kg);
        float w1 = wp[i], w2 = wg[i];
        a0 += w1 * mp;  a1 += w1;
        a2 += w2 * mg;  a3 += w2;
    }
#pragma unroll
    for (int o = 16; o > 0; o >>= 1) {
        a0 += __shfl_down_sync(0xffffffffu, a0, o);
        a1 += __shfl_down_sync(0xffffffffu, a1, o);
        a2 += __shfl_down_sync(0xffffffffu, a2, o);
        a3 += __shfl_down_sync(0xffffffffu, a3, o);
    }
    if (lane == 0) { sh[0][wid] = a0; sh[1][wid] = a1; sh[2][wid] = a2; sh[3][wid] = a3; }
    __syncthreads();
    if (tid == 0) {
        float t0 = 0.f, t1 = 0.f, t2 = 0.f, t3 = 0.f;
#pragma unroll
        for (int w = 0; w < 8; w++) { t0 += sh[0][w]; t1 += sh[1][w]; t2 += sh[2][w]; t3 += sh[3][w]; }
        g_part[b][0] = t0; g_part[b][1] = t1; g_part[b][2] = t2; g_part[b][3] = t3;
        __threadfence();
        s_ticket = atomicAdd(&g_ctr, 1u);
    }
    __syncthreads();
    if (s_ticket == 31u && tid == 0) {
        volatile float (*part)[4] = g_part;
        float s0 = 0.f, s1 = 0.f, s2 = 0.f, s3 = 0.f;
        for (int q = 0; q < 32; q++) {
            s0 += part[q][0]; s1 += part[q][1];
            s2 += part[q][2]; s3 += part[q][3];
        }
        out[0] = s0 / fmaxf(s1, 1e-9f) + s2 / fmaxf(s3, 1e-9f);
        g_ctr = 0u;   // reset for next replay
    }
}

// ---------------------------------------------------------------------------
extern "C" void kernel_launch(void* const* d_in, const int* in_sizes, int n_in,
                              void* d_out, int out_size) {
    const float* pred = (const float*)d_in[0];   // (P,3)
    const float* gt   = (const float*)d_in[1];   // (G,3)
    const float* wp   = (const float*)d_in[2];   // (P,)
    const float* wg   = (const float*)d_in[3];   // (G,)
    float* out = (float*)d_out;

    dim3 grid(NP / TILE, NY);
    k_pairs<<<grid, 256>>>(pred, gt);
    k_combine<<<32, 256>>>(wp, wg, out);
}